// round 17
// baseline (speedup 1.0000x reference)
#include <cuda_runtime.h>

#define BSZ 2
#define SEQ 4096
#define DIM 1024
#define CHUNK 16
#define NCHUNK (SEQ / CHUNK)   // 256

// ---- scratch ----
__device__ int   g_pos[BSZ * SEQ];
__device__ float g_pk [BSZ * SEQ];
__device__ float g_Pc [BSZ * NCHUNK];
__device__ int   g_nb [BSZ];
__device__ float g_E [BSZ * NCHUNK * DIM];
__device__ float g_S [BSZ * NCHUNK * DIM];

// ---------------------------------------------------------------------------
// Kernel 1: mask scan -> pos/pk/nb + per-chunk decay products.
// One block per batch, 1024 threads (4 elems each).
// ---------------------------------------------------------------------------
__global__ void prep_kernel(const float* __restrict__ prob,
                            const void* __restrict__ mask_raw) {
    const int b = blockIdx.x;
    const int t = threadIdx.x;

    __shared__ int   s_w;
    __shared__ int   s_wsum[32];
    __shared__ int   s_total;
    __shared__ float s_pk[SEQ];     // compacted clipped p (16 KB)

    // mask element-width detect (1-byte bool vs 4-byte 0/1)
    if (t == 0) s_w = 0;
    __syncthreads();
    {
        const unsigned char* mb = (const unsigned char*)mask_raw;
        int f = 0;
        for (int j = t; j < (BSZ * SEQ) / 4; j += blockDim.x)
            f |= mb[4 * j + 1];
        if (f) s_w = 1;
    }
    __syncthreads();
    const int onebyte = s_w;

    const int base = t * 4;
    int m[4];
    if (onebyte) {
        const unsigned char* mb = (const unsigned char*)mask_raw + b * SEQ;
        #pragma unroll
        for (int j = 0; j < 4; j++) m[j] = mb[base + j] ? 1 : 0;
    } else {
        const int* mi = (const int*)mask_raw + b * SEQ;
        #pragma unroll
        for (int j = 0; j < 4; j++) m[j] = mi[base + j] ? 1 : 0;
    }
    int cnt = m[0] + m[1] + m[2] + m[3];

    // block inclusive scan of per-thread counts
    int v = cnt;
    const int lane = t & 31, wid = t >> 5;
    #pragma unroll
    for (int o = 1; o < 32; o <<= 1) {
        int u = __shfl_up_sync(0xffffffffu, v, o);
        if (lane >= o) v += u;
    }
    if (lane == 31) s_wsum[wid] = v;
    __syncthreads();
    if (wid == 0) {
        int w = s_wsum[lane];
        #pragma unroll
        for (int o = 1; o < 32; o <<= 1) {
            int u = __shfl_up_sync(0xffffffffu, w, o);
            if (lane >= o) w += u;
        }
        s_wsum[lane] = w;
        if (lane == 31) s_total = w;
    }
    __syncthreads();

    int run = v - cnt + (wid ? s_wsum[wid - 1] : 0);
    const int nb = s_total;
    if (t == 0) g_nb[b] = nb;

    const float* pb = prob + b * SEQ;
    #pragma unroll
    for (int j = 0; j < 4; j++) {
        const int l = base + j;
        if (m[j]) {
            float p = pb[l];
            p = fminf(fmaxf(p, 1e-4f), 0.9999f);
            g_pos[b * SEQ + run] = l;
            g_pk [b * SEQ + run] = p;
            s_pk[run] = p;
            run++;
        }
    }
    __syncthreads();

    // per-chunk decay products: 16-lane shuffle groups over smem
    const int nc = (nb + CHUNK - 1) / CHUNK;
    const int half = lane >> 4;
    const int sub  = lane & 15;
    for (int c = wid * 2 + half; c < nc; c += 64) {
        const int k = c * CHUNK + sub;
        float a = (k < nb) ? (1.f - s_pk[k]) : 1.f;
        #pragma unroll
        for (int o = 8; o > 0; o >>= 1)
            a *= __shfl_xor_sync(0xffffffffu, a, o);
        if (sub == 0) g_Pc[b * NCHUNK + c] = a;
    }
}

// ---------------------------------------------------------------------------
// Kernel 2: chunk-local scan from zero -> chunk-end state g_E.
// grid (DIM/256, NCHUNK, BSZ), 256 threads, scalar channel per thread.
// ---------------------------------------------------------------------------
__global__ void escan_kernel(const float* __restrict__ hidden) {
    const int b = blockIdx.z, c = blockIdx.y;
    const int d = blockIdx.x * 256 + threadIdx.x;
    const int nb = g_nb[b];
    const int k0 = c * CHUNK;
    if (k0 >= nb) return;
    const int n = min(CHUNK, nb - k0);

    __shared__ int   spos[CHUNK];
    __shared__ float spk [CHUNK];
    if (threadIdx.x < n) {
        spos[threadIdx.x] = g_pos[b * SEQ + k0 + threadIdx.x];
        spk [threadIdx.x] = g_pk [b * SEQ + k0 + threadIdx.x];
    }
    __syncthreads();

    const float* hb = hidden + (size_t)b * SEQ * DIM + d;
    float h[CHUNK];
    #pragma unroll
    for (int j = 0; j < CHUNK; j++)
        h[j] = (j < n) ? __ldg(hb + (size_t)spos[j] * DIM) : 0.f;

    float s = 0.f;
    #pragma unroll
    for (int j = 0; j < CHUNK; j++) {
        if (j < n) {
            const float p = spk[j];
            s = fmaf(1.f - p, s, p * h[j]);
        }
    }
    g_E[(size_t)(b * NCHUNK + c) * DIM + d] = s;
}

// ---------------------------------------------------------------------------
// Kernel 3: serial combine across chunks -> g_S (exclusive incoming states).
// grid (DIM/256, BSZ), 256 threads scalar, 16-deep double-buffered prefetch.
// ---------------------------------------------------------------------------
__global__ void combine_kernel() {
    const int b = blockIdx.y;
    const int d = blockIdx.x * 256 + threadIdx.x;
    const int nb = g_nb[b];
    const int nc = (nb + CHUNK - 1) / CHUNK;

    const float* Eb = g_E + (size_t)(b * NCHUNK) * DIM + d;
    const float* Pb = g_Pc + b * NCHUNK;
    float*       Sb = g_S + (size_t)(b * NCHUNK) * DIM + d;

    float s = 0.f;
    const int G = 16;
    float Ebuf[G], Pbuf[G];
    #pragma unroll
    for (int j = 0; j < G; j++) {
        Ebuf[j] = (j < nc) ? Eb[(size_t)j * DIM] : 0.f;
        Pbuf[j] = (j < nc) ? Pb[j] : 1.f;
    }
    for (int g = 0; g < NCHUNK && g < nc; g += G) {
        float En[G], Pn[G];
        #pragma unroll
        for (int j = 0; j < G; j++) {
            const int cc = g + G + j;
            En[j] = (cc < nc) ? Eb[(size_t)cc * DIM] : 0.f;
            Pn[j] = (cc < nc) ? Pb[cc] : 1.f;
        }
        #pragma unroll
        for (int j = 0; j < G; j++) {
            const int cc = g + j;
            if (cc < nc) {
                Sb[(size_t)cc * DIM] = s;
                s = fmaf(Pbuf[j], s, Ebuf[j]);
            }
        }
        #pragma unroll
        for (int j = 0; j < G; j++) { Ebuf[j] = En[j]; Pbuf[j] = Pn[j]; }
    }
}

// ---------------------------------------------------------------------------
// Kernel 4: seeded rescan -> shared y staging -> independent streaming stores.
// grid (DIM/256, NCHUNK, BSZ) = 2048 CTAs, 256 threads, scalar channel.
// ---------------------------------------------------------------------------
__global__ void fused_out_kernel(const float* __restrict__ hidden,
                                 float* __restrict__ out) {
    const int b = blockIdx.z, c = blockIdx.y;
    const int d = blockIdx.x * 256 + threadIdx.x;
    const int t = threadIdx.x;
    const int nb = g_nb[b];
    const int k0 = c * CHUNK;
    if (k0 >= nb) return;
    const int n = min(CHUNK, nb - k0);

    __shared__ int           spos[CHUNK + 1];
    __shared__ float         spk [CHUNK];
    __shared__ float         s_y [CHUNK * 256];   // 16 KB: final token values (this d-slice)
    __shared__ unsigned char s_tok[SEQ];          // 4 KB max span: row -> local token

    if (t <= n) {
        const int kk = k0 + t;
        spos[t] = (kk < nb) ? g_pos[b * SEQ + kk] : SEQ;
    }
    if (t < n)
        spk[t] = g_pk[b * SEQ + k0 + t];
    __syncthreads();

    // --- phase A: seeded scan; park y_j in shared ---
    const float* hb = hidden + (size_t)b * SEQ * DIM + d;
    float h[CHUNK];
    #pragma unroll
    for (int j = 0; j < CHUNK; j++)
        h[j] = (j < n) ? __ldg(hb + (size_t)spos[j] * DIM) : 0.f;

    float s = g_S[(size_t)(b * NCHUNK + c) * DIM + d];
    #pragma unroll
    for (int j = 0; j < CHUNK; j++) {
        if (j < n) {
            const float p = spk[j];
            s = fmaf(1.f - p, s, p * h[j]);
            s_y[j * 256 + t] = s;
        }
    }

    // --- phase B: parallel row -> token map over this chunk's span ---
    const int rstart = (k0 == 0) ? 0 : spos[0];
    const int rend   = spos[n];       // sentinel: next chunk start or SEQ
    __syncthreads();                  // s_y + spos visible

    for (int r = rstart + t; r < rend; r += 256) {
        int j = 0;
        #pragma unroll
        for (int jj = 1; jj < CHUNK; jj++)
            if (jj < n && spos[jj] <= r) j = jj;
        s_tok[r - rstart] = (unsigned char)j;
    }
    __syncthreads();

    // --- phase C: independent streaming stores (unrolled, MLP>=4) ---
    float* ob = out + (size_t)b * SEQ * DIM + d;
    int r = rstart;
    const int span = rend - rstart;
    const int tail = rstart + (span & ~3);
    for (; r < tail; r += 4) {
        const int j0 = s_tok[r - rstart];
        const int j1 = s_tok[r - rstart + 1];
        const int j2 = s_tok[r - rstart + 2];
        const int j3 = s_tok[r - rstart + 3];
        const float y0 = s_y[j0 * 256 + t];
        const float y1 = s_y[j1 * 256 + t];
        const float y2 = s_y[j2 * 256 + t];
        const float y3 = s_y[j3 * 256 + t];
        ob[(size_t)(r + 0) * DIM] = y0;
        ob[(size_t)(r + 1) * DIM] = y1;
        ob[(size_t)(r + 2) * DIM] = y2;
        ob[(size_t)(r + 3) * DIM] = y3;
    }
    for (; r < rend; r++)
        ob[(size_t)r * DIM] = s_y[s_tok[r - rstart] * 256 + t];
}

// ---------------------------------------------------------------------------
extern "C" void kernel_launch(void* const* d_in, const int* in_sizes, int n_in,
                              void* d_out, int out_size) {
    const float* hidden = (const float*)d_in[0];
    const float* prob   = (const float*)d_in[1];
    const void*  mask   = d_in[2];
    float* out = (float*)d_out;

    prep_kernel<<<BSZ, 1024>>>(prob, mask);
    escan_kernel<<<dim3(DIM / 256, NCHUNK, BSZ), 256>>>(hidden);
    combine_kernel<<<dim3(DIM / 256, BSZ), 256>>>();
    fused_out_kernel<<<dim3(DIM / 256, NCHUNK, BSZ), 256>>>(hidden, out);
}